// round 14
// baseline (speedup 1.0000x reference)
#include <cuda_runtime.h>
#include <math.h>
#include <stdint.h>

#define B_  8
#define S_  1024
#define D_  768
#define H_  12
#define DP_ 64
#define GK  768

// Scratch (device globals: allocation-free per harness rules)
__device__ __align__(16) float g_qh[(size_t)B_*H_*S_*DP_];
__device__ __align__(16) float g_kh[(size_t)B_*H_*S_*DP_];
__device__ __align__(16) float g_vh[(size_t)B_*H_*S_*DP_];
__device__ __align__(16) float g_attn[(size_t)B_*S_*D_];

typedef unsigned long long ull;

// ---------------------------------------------------------------------------
// packed f32x2 helpers
// ---------------------------------------------------------------------------
__device__ __forceinline__ void ffma2(ull& c, ull a, ull b) {
    asm("fma.rn.f32x2 %0, %1, %2, %0;" : "+l"(c) : "l"(a), "l"(b));
}
__device__ __forceinline__ void fmul2(ull& c, ull a) {
    asm("mul.rn.f32x2 %0, %0, %1;" : "+l"(c) : "l"(a));
}
__device__ __forceinline__ ull splat2(float v) {
    ull p;
    asm("mov.b64 %0, {%1, %1};" : "=l"(p) : "f"(v));
    return p;
}
__device__ __forceinline__ float2 u2f2(ull x) {
    float2 r;
    r.x = __uint_as_float((unsigned)x);
    r.y = __uint_as_float((unsigned)(x >> 32));
    return r;
}

// ===========================================================================
// FFMA2 NT GEMM, K-chunk 32, double-buffered dynamic smem, multi-problem z.
// C[8192,768] = A[8192,768] @ W[768,768]^T + bias
// Block 128x128, 256 threads, 8 rows x 8 cols (4 f32x2) per thread.
// mode 1: out[((b*H+h)*S+s)*64+d]; mode 0: row-major [M,768].
// ===========================================================================
#define GP   132                      // smem k-row stride (floats)
#define KCH  32                       // k per chunk
#define STG  (KCH * GP)               // floats per array per stage (4224)
#define GEMM_SMEM (4 * STG * 4)       // 67584 B

struct QKVArgs {
    const float* A[3];
    const float* W[3];
    const float* bias[3];
    float*       out[3];
    int mode;
};

__global__ __launch_bounds__(256, 2) void gemm_f32x2(QKVArgs args)
{
    extern __shared__ __align__(16) float smem[];
    // As stage s: smem + s*STG ; Bs stage s: smem + 2*STG + s*STG

    const int z = blockIdx.z;
    const float* __restrict__ A    = args.A[z];
    const float* __restrict__ W    = args.W[z];
    const float* __restrict__ bias = args.bias[z];
    float* __restrict__ out        = args.out[z];
    const int mode = args.mode;

    const int tid = threadIdx.x;
    const int ty  = tid >> 4;    // 0..15
    const int tx  = tid & 15;    // 0..15
    const int m0  = blockIdx.y * 128;
    const int n0  = blockIdx.x * 128;

    // loader coords: row fixed per thread; quads kq0+2t, t=0..3
    const int row = tid & 127;
    const int kq0 = tid >> 7;    // 0 or 1

    const float* pa = &A[(size_t)(m0 + row) * GK + kq0 * 4];
    const float* pw = &W[(size_t)(n0 + row) * GK + kq0 * 4];

    ull c2[8][4];
#pragma unroll
    for (int i = 0; i < 8; i++)
#pragma unroll
        for (int j = 0; j < 4; j++) c2[i][j] = 0ull;

    float4 ra[4], rb[4];

    auto loadg = [&](int c) {
        const int k0 = c * KCH;
#pragma unroll
        for (int t = 0; t < 4; t++) {
            ra[t] = *(const float4*)(pa + k0 + 8 * t);
            rb[t] = *(const float4*)(pw + k0 + 8 * t);
        }
    };
    auto stss = [&](int s) {
        float* As = smem + s * STG;
        float* Bs = smem + 2 * STG + s * STG;
#pragma unroll
        for (int t = 0; t < 4; t++) {
            const int kb = (kq0 + 2 * t) * 4;   // k index base of this quad
            float va[4] = {ra[t].x, ra[t].y, ra[t].z, ra[t].w};
            float vb[4] = {rb[t].x, rb[t].y, rb[t].z, rb[t].w};
#pragma unroll
            for (int c = 0; c < 4; c++) {
                As[(kb + c) * GP + row] = va[c];
                Bs[(kb + c) * GP + row] = vb[c];
            }
        }
    };

    loadg(0);
    stss(0);
    __syncthreads();

    const int NIT = GK / KCH;   // 24
#pragma unroll 1
    for (int cc = 0; cc < NIT; cc++) {
        const int s = cc & 1;
        if (cc < NIT - 1) loadg(cc + 1);

        const float* As = smem + s * STG;
        const float* Bs = smem + 2 * STG + s * STG;
#pragma unroll
        for (int kk = 0; kk < KCH; kk++) {
            const float* as = &As[kk * GP + 8 * ty];
            float4 af0 = *(const float4*)as;
            float4 af1 = *(const float4*)(as + 4);
            ull a2[8];
            a2[0] = splat2(af0.x); a2[1] = splat2(af0.y);
            a2[2] = splat2(af0.z); a2[3] = splat2(af0.w);
            a2[4] = splat2(af1.x); a2[5] = splat2(af1.y);
            a2[6] = splat2(af1.z); a2[7] = splat2(af1.w);
            const float* bs = &Bs[kk * GP + 8 * tx];
            ulonglong2 bv0 = *(const ulonglong2*)bs;
            ulonglong2 bv1 = *(const ulonglong2*)(bs + 4);
            ull b2[4] = {bv0.x, bv0.y, bv1.x, bv1.y};
#pragma unroll
            for (int i = 0; i < 8; i++)
#pragma unroll
                for (int j = 0; j < 4; j++)
                    ffma2(c2[i][j], a2[i], b2[j]);
        }

        if (cc < NIT - 1) {
            stss(s ^ 1);
            __syncthreads();
        }
    }

    // Epilogue
#pragma unroll
    for (int i = 0; i < 8; i++) {
        int m  = m0 + 8 * ty + i;
        int bb = m >> 10;
        int ss = m & 1023;
#pragma unroll
        for (int jp = 0; jp < 4; jp++) {
            int n = n0 + 8 * tx + 2 * jp;
            float2 v = u2f2(c2[i][jp]);
            v.x += bias[n]; v.y += bias[n + 1];
            if (mode == 1) {
                int h = n >> 6, d = n & 63;
                *(float2*)&out[(((size_t)bb * H_ + h) * S_ + ss) * DP_ + d] = v;
            } else {
                *(float2*)&out[(size_t)m * D_ + n] = v;
            }
        }
    }
}

// ---------------------------------------------------------------------------
// Fused causal attention with relative-position (skew) bias. (round-7 proven)
// logits(i,j) = 0.125 * ( q_i·k_j + q_i·Er[1023-(i-j)] ),  j <= i
// Swizzled kk-major tiles (block-xor, t=(kk>>2)&7); ers padded stride 132.
// ---------------------------------------------------------------------------
#define EP 132

__global__ __launch_bounds__(256, 2) void attn_kernel(const float* __restrict__ Er)
{
    extern __shared__ float sm[];
    float* qs  = sm;               // [64][64]  kk-major, swizzled, *0.125
    float* ks  = qs  + 4096;       // [64][64]  kk-major, swizzled
    float* ers = ks  + 4096;       // [64][132] kk-major, padded
    float* vs  = ers + 64 * EP;    // [64][64]  jj-major, plain
    float* ps  = vs  + 4096;       // [64][64]  jj-major, swizzled

    const int tid = threadIdx.x;
    const int ty = tid >> 4;
    const int tx = tid & 15;
    const int i0 = blockIdx.x * 64;
    const int bh = blockIdx.y;

    const float* qp = g_qh + (size_t)bh * S_ * DP_;
    const float* kp = g_kh + (size_t)bh * S_ * DP_;
    const float* vp = g_vh + (size_t)bh * S_ * DP_;

    // Q tile: transpose+scale with swizzled store
    for (int idx = tid; idx < 1024; idx += 256) {
        int row = idx >> 4;
        int c4  = (idx & 15) << 2;
        int t   = (idx & 15) & 7;
        int so  = (((row >> 2) ^ t) << 2) | (row & 3);
        float4 v = *(const float4*)&qp[(size_t)(i0 + row) * DP_ + c4];
        qs[(c4+0)*64 + so] = v.x * 0.125f;
        qs[(c4+1)*64 + so] = v.y * 0.125f;
        qs[(c4+2)*64 + so] = v.z * 0.125f;
        qs[(c4+3)*64 + so] = v.w * 0.125f;
    }

    ull acc2[4][2];
#pragma unroll
    for (int i = 0; i < 4; i++) { acc2[i][0] = 0ull; acc2[i][1] = 0ull; }
    float mrow[4] = {-INFINITY, -INFINITY, -INFINITY, -INFINITY};
    float lrow[4] = {0.f, 0.f, 0.f, 0.f};

    const int ecol0 = 60 + 4*tx - 4*ty;   // 0..120, multiple of 4
    const int tps   = tx & 7;

    for (int j0 = 0; j0 <= i0; j0 += 64) {
        __syncthreads();   // ps/vs (prev PV) safe

        // K tile: transpose, swizzled
        for (int idx = tid; idx < 1024; idx += 256) {
            int row = idx >> 4;
            int c4  = (idx & 15) << 2;
            int t   = (idx & 15) & 7;
            int so  = (((row >> 2) ^ t) << 2) | (row & 3);
            float4 v = *(const float4*)&kp[(size_t)(j0 + row) * DP_ + c4];
            ks[(c4+0)*64 + so] = v.x;
            ks[(c4+1)*64 + so] = v.y;
            ks[(c4+2)*64 + so] = v.z;
            ks[(c4+3)*64 + so] = v.w;
        }
        // V tile: plain row-major
        for (int idx = tid; idx < 1024; idx += 256) {
            int row = idx >> 4;
            int c4  = (idx & 15) << 2;
            *(float4*)&vs[row*64 + c4] = *(const float4*)&vp[(size_t)(j0 + row) * DP_ + c4];
        }
        // Er band: transpose into padded rows (stride EP)
        int ebase = S_ - 64 - i0 + j0;
        for (int idx = tid; idx < 2048; idx += 256) {
            int e  = idx >> 4;
            int c4 = (idx & 15) << 2;
            float4 v = make_float4(0.f, 0.f, 0.f, 0.f);
            if (ebase + e < S_)
                v = *(const float4*)&Er[(size_t)(ebase + e) * DP_ + c4];
            ers[(c4+0)*EP + e] = v.x;
            ers[(c4+1)*EP + e] = v.y;
            ers[(c4+2)*EP + e] = v.z;
            ers[(c4+3)*EP + e] = v.w;
        }
        __syncthreads();

        // ---- S = Qs @ (K + shifted Er)^T ----
        float sacc[4][4];
#pragma unroll
        for (int i = 0; i < 4; i++)
#pragma unroll
            for (int j = 0; j < 4; j++) sacc[i][j] = 0.f;

#pragma unroll 4
        for (int kkb = 0; kkb < 16; kkb++) {
            const int t = kkb & 7;
            const float* qb = &qs[kkb*256 + ((ty ^ t) << 2)];
            const float* kb = &ks[kkb*256 + ((tx ^ t) << 2)];
            const float* eb = &ers[kkb*4*EP + ecol0];
#pragma unroll
            for (int c = 0; c < 4; c++) {
                float4 qf = *(const float4*)&qb[c*64];
                float4 kf = *(const float4*)&kb[c*64];
                float4 e0 = *(const float4*)&eb[c*EP];
                float4 e1 = *(const float4*)&eb[c*EP + 4];
                float qa[4] = {qf.x, qf.y, qf.z, qf.w};
                float ka[4] = {kf.x, kf.y, kf.z, kf.w};
                float er7[7] = {e0.x, e0.y, e0.z, e0.w, e1.x, e1.y, e1.z};
#pragma unroll
                for (int ri = 0; ri < 4; ri++)
#pragma unroll
                    for (int ci = 0; ci < 4; ci++)
                        sacc[ri][ci] += qa[ri] * (ka[ci] + er7[3 - ri + ci]);
            }
        }

        if (j0 == i0) {
#pragma unroll
            for (int ri = 0; ri < 4; ri++)
#pragma unroll
                for (int ci = 0; ci < 4; ci++)
                    if (j0 + 4*tx + ci > i0 + 4*ty + ri) sacc[ri][ci] = -1e30f;
        }

#pragma unroll
        for (int ri = 0; ri < 4; ri++) {
            float mn = fmaxf(fmaxf(sacc[ri][0], sacc[ri][1]),
                             fmaxf(sacc[ri][2], sacc[ri][3]));
#pragma unroll
            for (int off = 8; off > 0; off >>= 1)
                mn = fmaxf(mn, __shfl_xor_sync(0xffffffffu, mn, off));
            float mt   = fmaxf(mrow[ri], mn);
            float corr = __expf(mrow[ri] - mt);
            mrow[ri]   = mt;
            float psum = 0.f;
#pragma unroll
            for (int ci = 0; ci < 4; ci++) {
                float p = __expf(sacc[ri][ci] - mt);
                sacc[ri][ci] = p;
                psum += p;
            }
#pragma unroll
            for (int off = 8; off > 0; off >>= 1)
                psum += __shfl_xor_sync(0xffffffffu, psum, off);
            lrow[ri] = lrow[ri] * corr + psum;
            ull cr = splat2(corr);
            fmul2(acc2[ri][0], cr);
            fmul2(acc2[ri][1], cr);
        }

        // store P transposed, swizzled: row jj=4tx+ci, col 4ty+ri
#pragma unroll
        for (int ci = 0; ci < 4; ci++) {
            int base = (4*tx + ci)*64 + (((ty ^ tps) << 2));
#pragma unroll
            for (int ri = 0; ri < 4; ri++)
                ps[base + ri] = sacc[ri][ci];
        }
        __syncthreads();

        // ---- O += P @ V  (FFMA2, p splats from one LDS.128) ----
#pragma unroll 4
        for (int jjb = 0; jjb < 16; jjb++) {
            const int t = jjb & 7;
            const float* pb = &ps[jjb*256 + ((ty ^ t) << 2)];
            const float* vb = &vs[jjb*256 + 4*tx];
#pragma unroll
            for (int c = 0; c < 4; c++) {
                float4 pf = *(const float4*)&pb[c*64];
                ulonglong2 vv = *(const ulonglong2*)&vb[c*64];
                ull p0 = splat2(pf.x), p1 = splat2(pf.y);
                ull p2 = splat2(pf.z), p3 = splat2(pf.w);
                ffma2(acc2[0][0], p0, vv.x); ffma2(acc2[0][1], p0, vv.y);
                ffma2(acc2[1][0], p1, vv.x); ffma2(acc2[1][1], p1, vv.y);
                ffma2(acc2[2][0], p2, vv.x); ffma2(acc2[2][1], p2, vv.y);
                ffma2(acc2[3][0], p3, vv.x); ffma2(acc2[3][1], p3, vv.y);
            }
        }
    }

    const int b = bh / H_;
    const int h = bh % H_;
#pragma unroll
    for (int ri = 0; ri < 4; ri++) {
        int i = i0 + 4*ty + ri;
        float inv = 1.f / lrow[ri];
        float2 v0 = u2f2(acc2[ri][0]);
        float2 v1 = u2f2(acc2[ri][1]);
        float4 v = make_float4(v0.x * inv, v0.y * inv, v1.x * inv, v1.y * inv);
        *(float4*)&g_attn[((size_t)b * S_ + i) * D_ + h * DP_ + 4*tx] = v;
    }
}

// ---------------------------------------------------------------------------
extern "C" void kernel_launch(void* const* d_in, const int* in_sizes, int n_in,
                              void* d_out, int out_size)
{
    const float* Q  = (const float*)d_in[0];
    const float* K  = (const float*)d_in[1];
    const float* V  = (const float*)d_in[2];
    const float* Wq = (const float*)d_in[4];
    const float* bq = (const float*)d_in[5];
    const float* Wk = (const float*)d_in[6];
    const float* bk = (const float*)d_in[7];
    const float* Wv = (const float*)d_in[8];
    const float* bv = (const float*)d_in[9];
    const float* Wo = (const float*)d_in[10];
    const float* bo = (const float*)d_in[11];
    const float* Er = (const float*)d_in[12];
    float* out = (float*)d_out;

    float *qh, *kh, *vh, *attn;
    cudaGetSymbolAddress((void**)&qh,   g_qh);
    cudaGetSymbolAddress((void**)&kh,   g_kh);
    cudaGetSymbolAddress((void**)&vh,   g_vh);
    cudaGetSymbolAddress((void**)&attn, g_attn);

    cudaFuncSetAttribute(gemm_f32x2,
                         cudaFuncAttributeMaxDynamicSharedMemorySize, GEMM_SMEM);

    // Fused Q/K/V projections: one launch, gridDim.z = 3
    QKVArgs qkv;
    qkv.A[0] = Q;  qkv.A[1] = K;  qkv.A[2] = V;
    qkv.W[0] = Wq; qkv.W[1] = Wk; qkv.W[2] = Wv;
    qkv.bias[0] = bq; qkv.bias[1] = bk; qkv.bias[2] = bv;
    qkv.out[0] = qh; qkv.out[1] = kh; qkv.out[2] = vh;
    qkv.mode = 1;
    gemm_f32x2<<<dim3(D_ / 128, (B_ * S_) / 128, 3), 256, GEMM_SMEM>>>(qkv);

    const int attn_smem = (4096 * 4 + 64 * EP) * (int)sizeof(float);   // ~97 KB
    cudaFuncSetAttribute(attn_kernel,
                         cudaFuncAttributeMaxDynamicSharedMemorySize, attn_smem);
    attn_kernel<<<dim3(S_ / 64, B_ * H_), 256, attn_smem>>>(Er);

    // Output projection
    QKVArgs oarg;
    oarg.A[0] = attn; oarg.A[1] = attn; oarg.A[2] = attn;
    oarg.W[0] = Wo;   oarg.W[1] = Wo;   oarg.W[2] = Wo;
    oarg.bias[0] = bo; oarg.bias[1] = bo; oarg.bias[2] = bo;
    oarg.out[0] = out; oarg.out[1] = out; oarg.out[2] = out;
    oarg.mode = 0;
    gemm_f32x2<<<dim3(D_ / 128, (B_ * S_) / 128, 1), 256, GEMM_SMEM>>>(oarg);
}

// round 16
// speedup vs baseline: 1.1549x; 1.1549x over previous
#include <cuda_runtime.h>
#include <math.h>
#include <stdint.h>

#define B_  8
#define S_  1024
#define D_  768
#define H_  12
#define DP_ 64
#define GK  768

// Scratch (device globals: allocation-free per harness rules)
__device__ __align__(16) float g_qh[(size_t)B_*H_*S_*DP_];
__device__ __align__(16) float g_kh[(size_t)B_*H_*S_*DP_];
__device__ __align__(16) float g_vh[(size_t)B_*H_*S_*DP_];
__device__ __align__(16) float g_attn[(size_t)B_*S_*D_];

typedef unsigned long long ull;

// ---------------------------------------------------------------------------
// packed f32x2 helpers
// ---------------------------------------------------------------------------
__device__ __forceinline__ void ffma2(ull& c, ull a, ull b) {
    asm("fma.rn.f32x2 %0, %1, %2, %0;" : "+l"(c) : "l"(a), "l"(b));
}
__device__ __forceinline__ void fmul2(ull& c, ull a) {
    asm("mul.rn.f32x2 %0, %0, %1;" : "+l"(c) : "l"(a));
}
__device__ __forceinline__ ull splat2(float v) {
    ull p;
    asm("mov.b64 %0, {%1, %1};" : "=l"(p) : "f"(v));
    return p;
}
__device__ __forceinline__ float2 u2f2(ull x) {
    float2 r;
    r.x = __uint_as_float((unsigned)x);
    r.y = __uint_as_float((unsigned)(x >> 32));
    return r;
}

// ===========================================================================
// FFMA2 NT GEMM (round-7 proven version, verbatim).
// C[8192,768] = A[8192,768] @ W[768,768]^T + bias
// Block 128x128, K-step 16, 256 threads, 8 rows x 8 cols (4 f32x2) / thread.
// mode 1: out[((b*H+h)*S+s)*64+d]; mode 0: row-major [M,768].
// ===========================================================================
#define GP 132     // padded smem row stride (floats)

struct QKVArgs {
    const float* A[3];
    const float* W[3];
    const float* bias[3];
    float*       out[3];
    int mode;
};

__global__ __launch_bounds__(256, 2) void gemm_f32x2(QKVArgs args)
{
    __shared__ __align__(16) float As[2][16 * GP];
    __shared__ __align__(16) float Bs[2][16 * GP];

    const int z = blockIdx.z;
    const float* __restrict__ A    = args.A[z];
    const float* __restrict__ W    = args.W[z];
    const float* __restrict__ bias = args.bias[z];
    float* __restrict__ out        = args.out[z];
    const int mode = args.mode;

    const int tid = threadIdx.x;
    const int ty  = tid >> 4;    // 0..15
    const int tx  = tid & 15;    // 0..15
    const int m0  = blockIdx.y * 128;
    const int n0  = blockIdx.x * 128;

    const int lr0 = tid >> 2;    // 0..63
    const int lkg = tid & 3;     // 0..3
    const int c4  = lkg * 4;

    const float* pa0 = &A[(size_t)(m0 + lr0)      * GK + c4];
    const float* pa1 = &A[(size_t)(m0 + lr0 + 64) * GK + c4];
    const float* pw0 = &W[(size_t)(n0 + lr0)      * GK + c4];
    const float* pw1 = &W[(size_t)(n0 + lr0 + 64) * GK + c4];

    ull c2[8][4];
#pragma unroll
    for (int i = 0; i < 8; i++)
#pragma unroll
        for (int j = 0; j < 4; j++) c2[i][j] = 0ull;

    float4 ra0, ra1, rb0, rb1;

    auto loadg = [&](int c) {
        const int k0 = c * 16;
        ra0 = *(const float4*)(pa0 + k0);
        ra1 = *(const float4*)(pa1 + k0);
        rb0 = *(const float4*)(pw0 + k0);
        rb1 = *(const float4*)(pw1 + k0);
    };
    auto stss = [&](int s) {
        float va0[4] = {ra0.x, ra0.y, ra0.z, ra0.w};
        float va1[4] = {ra1.x, ra1.y, ra1.z, ra1.w};
        float vb0[4] = {rb0.x, rb0.y, rb0.z, rb0.w};
        float vb1[4] = {rb1.x, rb1.y, rb1.z, rb1.w};
#pragma unroll
        for (int c = 0; c < 4; c++) {
            As[s][(c4 + c) * GP + lr0]      = va0[c];
            As[s][(c4 + c) * GP + lr0 + 64] = va1[c];
            Bs[s][(c4 + c) * GP + lr0]      = vb0[c];
            Bs[s][(c4 + c) * GP + lr0 + 64] = vb1[c];
        }
    };

    loadg(0);
    stss(0);
    __syncthreads();

    const int NIT = GK / 16;   // 48
#pragma unroll 1
    for (int cc = 0; cc < NIT; cc++) {
        const int s = cc & 1;
        if (cc < NIT - 1) loadg(cc + 1);

#pragma unroll
        for (int kk = 0; kk < 16; kk++) {
            const float* as = &As[s][kk * GP + 8 * ty];
            float4 af0 = *(const float4*)as;
            float4 af1 = *(const float4*)(as + 4);
            ull a2[8];
            a2[0] = splat2(af0.x); a2[1] = splat2(af0.y);
            a2[2] = splat2(af0.z); a2[3] = splat2(af0.w);
            a2[4] = splat2(af1.x); a2[5] = splat2(af1.y);
            a2[6] = splat2(af1.z); a2[7] = splat2(af1.w);
            const float* bs = &Bs[s][kk * GP + 8 * tx];
            ulonglong2 bv0 = *(const ulonglong2*)bs;
            ulonglong2 bv1 = *(const ulonglong2*)(bs + 4);
            ull b2[4] = {bv0.x, bv0.y, bv1.x, bv1.y};
#pragma unroll
            for (int i = 0; i < 8; i++)
#pragma unroll
                for (int j = 0; j < 4; j++)
                    ffma2(c2[i][j], a2[i], b2[j]);
        }

        if (cc < NIT - 1) {
            stss(s ^ 1);
            __syncthreads();
        }
    }

    // Epilogue
#pragma unroll
    for (int i = 0; i < 8; i++) {
        int m  = m0 + 8 * ty + i;
        int bb = m >> 10;
        int ss = m & 1023;
#pragma unroll
        for (int jp = 0; jp < 4; jp++) {
            int n = n0 + 8 * tx + 2 * jp;
            float2 v = u2f2(c2[i][jp]);
            v.x += bias[n]; v.y += bias[n + 1];
            if (mode == 1) {
                int h = n >> 6, d = n & 63;
                *(float2*)&out[(((size_t)bb * H_ + h) * S_ + ss) * DP_ + d] = v;
            } else {
                *(float2*)&out[(size_t)m * D_ + n] = v;
            }
        }
    }
}

// ---------------------------------------------------------------------------
// Fused causal attention with relative-position (skew) bias. (round-7 proven)
// logits(i,j) = 0.125 * ( q_i·k_j + q_i·Er[1023-(i-j)] ),  j <= i
// Swizzled kk-major tiles (block-xor, t=(kk>>2)&7); ers padded stride 132.
// LPT scheduling: blockIdx.x REVERSED so longest blocks (most j-tiles)
// dispatch first; short blocks fill the final-wave tail.
// ---------------------------------------------------------------------------
#define EP 132

__global__ __launch_bounds__(256, 2) void attn_kernel(const float* __restrict__ Er)
{
    extern __shared__ float sm[];
    float* qs  = sm;               // [64][64]  kk-major, swizzled, *0.125
    float* ks  = qs  + 4096;       // [64][64]  kk-major, swizzled
    float* ers = ks  + 4096;       // [64][132] kk-major, padded
    float* vs  = ers + 64 * EP;    // [64][64]  jj-major, plain
    float* ps  = vs  + 4096;       // [64][64]  jj-major, swizzled

    const int tid = threadIdx.x;
    const int ty = tid >> 4;
    const int tx = tid & 15;
    const int i0 = ((int)gridDim.x - 1 - (int)blockIdx.x) * 64;   // LPT: long blocks first
    const int bh = blockIdx.y;

    const float* qp = g_qh + (size_t)bh * S_ * DP_;
    const float* kp = g_kh + (size_t)bh * S_ * DP_;
    const float* vp = g_vh + (size_t)bh * S_ * DP_;

    // Q tile: transpose+scale with swizzled store
    for (int idx = tid; idx < 1024; idx += 256) {
        int row = idx >> 4;
        int c4  = (idx & 15) << 2;
        int t   = (idx & 15) & 7;
        int so  = (((row >> 2) ^ t) << 2) | (row & 3);
        float4 v = *(const float4*)&qp[(size_t)(i0 + row) * DP_ + c4];
        qs[(c4+0)*64 + so] = v.x * 0.125f;
        qs[(c4+1)*64 + so] = v.y * 0.125f;
        qs[(c4+2)*64 + so] = v.z * 0.125f;
        qs[(c4+3)*64 + so] = v.w * 0.125f;
    }

    ull acc2[4][2];
#pragma unroll
    for (int i = 0; i < 4; i++) { acc2[i][0] = 0ull; acc2[i][1] = 0ull; }
    float mrow[4] = {-INFINITY, -INFINITY, -INFINITY, -INFINITY};
    float lrow[4] = {0.f, 0.f, 0.f, 0.f};

    const int ecol0 = 60 + 4*tx - 4*ty;   // 0..120, multiple of 4
    const int tps   = tx & 7;

    for (int j0 = 0; j0 <= i0; j0 += 64) {
        __syncthreads();   // ps/vs (prev PV) safe

        // K tile: transpose, swizzled
        for (int idx = tid; idx < 1024; idx += 256) {
            int row = idx >> 4;
            int c4  = (idx & 15) << 2;
            int t   = (idx & 15) & 7;
            int so  = (((row >> 2) ^ t) << 2) | (row & 3);
            float4 v = *(const float4*)&kp[(size_t)(j0 + row) * DP_ + c4];
            ks[(c4+0)*64 + so] = v.x;
            ks[(c4+1)*64 + so] = v.y;
            ks[(c4+2)*64 + so] = v.z;
            ks[(c4+3)*64 + so] = v.w;
        }
        // V tile: plain row-major
        for (int idx = tid; idx < 1024; idx += 256) {
            int row = idx >> 4;
            int c4  = (idx & 15) << 2;
            *(float4*)&vs[row*64 + c4] = *(const float4*)&vp[(size_t)(j0 + row) * DP_ + c4];
        }
        // Er band: transpose into padded rows (stride EP)
        int ebase = S_ - 64 - i0 + j0;
        for (int idx = tid; idx < 2048; idx += 256) {
            int e  = idx >> 4;
            int c4 = (idx & 15) << 2;
            float4 v = make_float4(0.f, 0.f, 0.f, 0.f);
            if (ebase + e < S_)
                v = *(const float4*)&Er[(size_t)(ebase + e) * DP_ + c4];
            ers[(c4+0)*EP + e] = v.x;
            ers[(c4+1)*EP + e] = v.y;
            ers[(c4+2)*EP + e] = v.z;
            ers[(c4+3)*EP + e] = v.w;
        }
        __syncthreads();

        // ---- S = Qs @ (K + shifted Er)^T ----
        float sacc[4][4];
#pragma unroll
        for (int i = 0; i < 4; i++)
#pragma unroll
            for (int j = 0; j < 4; j++) sacc[i][j] = 0.f;

#pragma unroll 4
        for (int kkb = 0; kkb < 16; kkb++) {
            const int t = kkb & 7;
            const float* qb = &qs[kkb*256 + ((ty ^ t) << 2)];
            const float* kb = &ks[kkb*256 + ((tx ^ t) << 2)];
            const float* eb = &ers[kkb*4*EP + ecol0];
#pragma unroll
            for (int c = 0; c < 4; c++) {
                float4 qf = *(const float4*)&qb[c*64];
                float4 kf = *(const float4*)&kb[c*64];
                float4 e0 = *(const float4*)&eb[c*EP];
                float4 e1 = *(const float4*)&eb[c*EP + 4];
                float qa[4] = {qf.x, qf.y, qf.z, qf.w};
                float ka[4] = {kf.x, kf.y, kf.z, kf.w};
                float er7[7] = {e0.x, e0.y, e0.z, e0.w, e1.x, e1.y, e1.z};
#pragma unroll
                for (int ri = 0; ri < 4; ri++)
#pragma unroll
                    for (int ci = 0; ci < 4; ci++)
                        sacc[ri][ci] += qa[ri] * (ka[ci] + er7[3 - ri + ci]);
            }
        }

        if (j0 == i0) {
#pragma unroll
            for (int ri = 0; ri < 4; ri++)
#pragma unroll
                for (int ci = 0; ci < 4; ci++)
                    if (j0 + 4*tx + ci > i0 + 4*ty + ri) sacc[ri][ci] = -1e30f;
        }

#pragma unroll
        for (int ri = 0; ri < 4; ri++) {
            float mn = fmaxf(fmaxf(sacc[ri][0], sacc[ri][1]),
                             fmaxf(sacc[ri][2], sacc[ri][3]));
#pragma unroll
            for (int off = 8; off > 0; off >>= 1)
                mn = fmaxf(mn, __shfl_xor_sync(0xffffffffu, mn, off));
            float mt   = fmaxf(mrow[ri], mn);
            float corr = __expf(mrow[ri] - mt);
            mrow[ri]   = mt;
            float psum = 0.f;
#pragma unroll
            for (int ci = 0; ci < 4; ci++) {
                float p = __expf(sacc[ri][ci] - mt);
                sacc[ri][ci] = p;
                psum += p;
            }
#pragma unroll
            for (int off = 8; off > 0; off >>= 1)
                psum += __shfl_xor_sync(0xffffffffu, psum, off);
            lrow[ri] = lrow[ri] * corr + psum;
            ull cr = splat2(corr);
            fmul2(acc2[ri][0], cr);
            fmul2(acc2[ri][1], cr);
        }

        // store P transposed, swizzled: row jj=4tx+ci, col 4ty+ri
#pragma unroll
        for (int ci = 0; ci < 4; ci++) {
            int base = (4*tx + ci)*64 + (((ty ^ tps) << 2));
#pragma unroll
            for (int ri = 0; ri < 4; ri++)
                ps[base + ri] = sacc[ri][ci];
        }
        __syncthreads();

        // ---- O += P @ V  (FFMA2, p splats from one LDS.128) ----
#pragma unroll 4
        for (int jjb = 0; jjb < 16; jjb++) {
            const int t = jjb & 7;
            const float* pb = &ps[jjb*256 + ((ty ^ t) << 2)];
            const float* vb = &vs[jjb*256 + 4*tx];
#pragma unroll
            for (int c = 0; c < 4; c++) {
                float4 pf = *(const float4*)&pb[c*64];
                ulonglong2 vv = *(const ulonglong2*)&vb[c*64];
                ull p0 = splat2(pf.x), p1 = splat2(pf.y);
                ull p2 = splat2(pf.z), p3 = splat2(pf.w);
                ffma2(acc2[0][0], p0, vv.x); ffma2(acc2[0][1], p0, vv.y);
                ffma2(acc2[1][0], p1, vv.x); ffma2(acc2[1][1], p1, vv.y);
                ffma2(acc2[2][0], p2, vv.x); ffma2(acc2[2][1], p2, vv.y);
                ffma2(acc2[3][0], p3, vv.x); ffma2(acc2[3][1], p3, vv.y);
            }
        }
    }

    const int b = bh / H_;
    const int h = bh % H_;
#pragma unroll
    for (int ri = 0; ri < 4; ri++) {
        int i = i0 + 4*ty + ri;
        float inv = 1.f / lrow[ri];
        float2 v0 = u2f2(acc2[ri][0]);
        float2 v1 = u2f2(acc2[ri][1]);
        float4 v = make_float4(v0.x * inv, v0.y * inv, v1.x * inv, v1.y * inv);
        *(float4*)&g_attn[((size_t)b * S_ + i) * D_ + h * DP_ + 4*tx] = v;
    }
}

// ---------------------------------------------------------------------------
extern "C" void kernel_launch(void* const* d_in, const int* in_sizes, int n_in,
                              void* d_out, int out_size)
{
    const float* Q  = (const float*)d_in[0];
    const float* K  = (const float*)d_in[1];
    const float* V  = (const float*)d_in[2];
    const float* Wq = (const float*)d_in[4];
    const float* bq = (const float*)d_in[5];
    const float* Wk = (const float*)d_in[6];
    const float* bk = (const float*)d_in[7];
    const float* Wv = (const float*)d_in[8];
    const float* bv = (const float*)d_in[9];
    const float* Wo = (const float*)d_in[10];
    const float* bo = (const float*)d_in[11];
    const float* Er = (const float*)d_in[12];
    float* out = (float*)d_out;

    float *qh, *kh, *vh, *attn;
    cudaGetSymbolAddress((void**)&qh,   g_qh);
    cudaGetSymbolAddress((void**)&kh,   g_kh);
    cudaGetSymbolAddress((void**)&vh,   g_vh);
    cudaGetSymbolAddress((void**)&attn, g_attn);

    // Fused Q/K/V projections: one launch, gridDim.z = 3
    QKVArgs qkv;
    qkv.A[0] = Q;  qkv.A[1] = K;  qkv.A[2] = V;
    qkv.W[0] = Wq; qkv.W[1] = Wk; qkv.W[2] = Wv;
    qkv.bias[0] = bq; qkv.bias[1] = bk; qkv.bias[2] = bv;
    qkv.out[0] = qh; qkv.out[1] = kh; qkv.out[2] = vh;
    qkv.mode = 1;
    gemm_f32x2<<<dim3(D_ / 128, (B_ * S_) / 128, 3), 256>>>(qkv);

    const int attn_smem = (4096 * 4 + 64 * EP) * (int)sizeof(float);   // ~97 KB
    cudaFuncSetAttribute(attn_kernel,
                         cudaFuncAttributeMaxDynamicSharedMemorySize, attn_smem);
    attn_kernel<<<dim3(S_ / 64, B_ * H_), 256, attn_smem>>>(Er);

    // Output projection
    QKVArgs oarg;
    oarg.A[0] = attn; oarg.A[1] = attn; oarg.A[2] = attn;
    oarg.W[0] = Wo;   oarg.W[1] = Wo;   oarg.W[2] = Wo;
    oarg.bias[0] = bo; oarg.bias[1] = bo; oarg.bias[2] = bo;
    oarg.out[0] = out; oarg.out[1] = out; oarg.out[2] = out;
    oarg.mode = 0;
    gemm_f32x2<<<dim3(D_ / 128, (B_ * S_) / 128, 1), 256>>>(oarg);
}